// round 5
// baseline (speedup 1.0000x reference)
#include <cuda_runtime.h>
#include <math.h>

#define NN 231
#define BT 8
#define THREADS 512
#define NWARP 16
#define MAXM 4096
#define CAP  2112

#define S1S 68    // t1 row stride (floats): 64 data + 4 pad (mult of 4!)
#define S2S 36    // t2 row stride: 32 + 4 (mult of 4)
#define T3S 20    // t3 row stride: 16 + 4
#define XFS 476   // FC input stride per graph (462 + pad)
#define H1S 124   // FC1 out stride (120 + 4)
#define H2S 92    // FC2 out stride (84 + 8)

// ---------------- persistent CSR built by prep kernel ----------------
__device__ int   g_row_ptr[NN + 1];
__device__ int   g_csr_src[MAXM];
__device__ float g_csr_w[MAXM];

// =====================================================================
// Prep kernel: deterministic CSR (stable counting sort by dst) + norms.
// =====================================================================
__global__ void prep_kernel(const void* __restrict__ ei, int E) {
    __shared__ short s_src[2304];
    __shared__ short s_dst[2304];
    __shared__ int   deg[NN];
    __shared__ int   rp[NN + 1];
    __shared__ float inv[NN];
    __shared__ int   cnt[32][NN];
    __shared__ int   is64;

    const int tid = threadIdx.x;
    const int M = E + NN;

    if (tid == 0) {
        const long long* p = (const long long*)ei;
        int ok = 1;
        for (int i = 0; i < 8; i++) {
            long long v = p[i];
            if (v < 0 || v >= NN) ok = 0;
        }
        is64 = ok;
    }
    for (int n = tid; n < NN; n += blockDim.x) deg[n] = 0;
    __syncthreads();

    for (int e = tid; e < M; e += blockDim.x) {
        int s, d;
        if (e < E) {
            if (is64) {
                s = (int)((const long long*)ei)[e];
                d = (int)((const long long*)ei)[E + e];
            } else {
                s = ((const int*)ei)[e];
                d = ((const int*)ei)[E + e];
            }
        } else {
            s = d = e - E;
        }
        s_src[e] = (short)s;
        s_dst[e] = (short)d;
        atomicAdd(&deg[d], 1);
    }
    __syncthreads();

    for (int n = tid; n < NN; n += blockDim.x)
        inv[n] = rsqrtf((float)max(deg[n], 1));
    if (tid == 0) {
        int acc = 0;
        for (int n = 0; n < NN; n++) { rp[n] = acc; acc += deg[n]; }
        rp[NN] = acc;
    }
    for (int i = tid; i < 32 * NN; i += blockDim.x)
        ((int*)cnt)[i] = 0;
    __syncthreads();

    const int chunk = (M + 31) / 32;
    if (tid < 32) {
        int e0 = tid * chunk, e1 = min(e0 + chunk, M);
        for (int e = e0; e < e1; e++) cnt[tid][s_dst[e]]++;
    }
    __syncthreads();

    for (int n = tid; n < NN; n += blockDim.x) {
        int run = rp[n];
        for (int t = 0; t < 32; t++) {
            int c = cnt[t][n];
            cnt[t][n] = run;
            run += c;
        }
    }
    __syncthreads();

    if (tid < 32) {
        int e0 = tid * chunk, e1 = min(e0 + chunk, M);
        for (int e = e0; e < e1; e++) {
            int d = s_dst[e], s = s_src[e];
            int pos = cnt[tid][d]++;
            g_csr_src[pos] = s;
            g_csr_w[pos]   = inv[s] * inv[d];
        }
    }
    __syncthreads();
    for (int n = tid; n <= NN; n += blockDim.x) g_row_ptr[n] = rp[n];
}

// =====================================================================
__device__ __forceinline__ float fast_tanh(float x) {
    x = fminf(fmaxf(x, -15.0f), 15.0f);
    float e = __expf(2.0f * x);
    return (e - 1.0f) / (e + 1.0f);
}
__device__ __forceinline__ float elu1(float v) {
    return v > 0.0f ? v : (__expf(v) - 1.0f);
}

// small-weight shared offsets (floats)
#define O_W1  0      // 12x8
#define O_B1  96     // 8
#define O_W2  104    // 8x4
#define O_B2  136    // 4
#define O_W3  140    // 4x2
#define O_B3  148    // 2
#define O_BF1 152    // 120
#define O_BF2 272    // 84
#define O_BF3 356    // 10
#define SMALLSZ 384

// smem: S1 + S2 + s_e(float2) + small (floats) + rp (int)
#define SM_FLOATS (NN*S1S + NN*S2S + 2*CAP + SMALLSZ)
#define SM_BYTES  (SM_FLOATS*4 + (NN+1)*4)

__global__ void __launch_bounds__(THREADS, 2)
gcn_fused_kernel(const float* __restrict__ x,
                 const float* __restrict__ W1, const float* __restrict__ b1,
                 const float* __restrict__ W2, const float* __restrict__ b2,
                 const float* __restrict__ W3, const float* __restrict__ b3,
                 const float* __restrict__ Wf1, const float* __restrict__ bf1,
                 const float* __restrict__ Wf2, const float* __restrict__ bf2,
                 const float* __restrict__ Wf3, const float* __restrict__ bf3,
                 float* __restrict__ out, int B, int M) {
    extern __shared__ float sm[];
    float*  S1      = sm;                        // t1 rows [n][8f][8b] str 68
    float*  S2      = S1 + NN * S1S;             // t2 rows [n][4f][8b] str 36
    float2* s_e     = (float2*)(S2 + NN * S2S);  // (w, src-bits)
    float*  s_small = (float*)(s_e + CAP);
    int*    s_rp    = (int*)(s_small + SMALLSZ);

    const int tid  = threadIdx.x;
    const int wid  = tid >> 5;
    const int lane = tid & 31;
    const int b0   = blockIdx.x * BT;

    // ---- stage CSR + small weights ----
    for (int i = tid; i <= NN; i += THREADS) s_rp[i] = g_row_ptr[i];
    for (int i = tid; i < M; i += THREADS)
        s_e[i] = make_float2(g_csr_w[i], __int_as_float(g_csr_src[i]));
    for (int i = tid; i < 96;  i += THREADS) s_small[O_W1 + i] = W1[i];
    for (int i = tid; i < 8;   i += THREADS) s_small[O_B1 + i] = b1[i];
    for (int i = tid; i < 32;  i += THREADS) s_small[O_W2 + i] = W2[i];
    for (int i = tid; i < 4;   i += THREADS) s_small[O_B2 + i] = b2[i];
    for (int i = tid; i < 8;   i += THREADS) s_small[O_W3 + i] = W3[i];
    for (int i = tid; i < 2;   i += THREADS) s_small[O_B3 + i] = b3[i];
    for (int i = tid; i < 120; i += THREADS) s_small[O_BF1 + i] = bf1[i];
    for (int i = tid; i < 84;  i += THREADS) s_small[O_BF2 + i] = bf2[i];
    for (int i = tid; i < 10;  i += THREADS) s_small[O_BF3 + i] = bf3[i];
    __syncthreads();

    // ========== T1: t1 = x @ W1 -> S1[n][f][b] (no bias) ==========
    for (int idx = tid; idx < NN * BT; idx += THREADS) {
        const int b = idx / NN, n = idx - b * NN;
        const int g = b0 + b;
        const float4* xp = (const float4*)(x + ((size_t)g * NN + n) * 12);
        float4 v0 = xp[0], v1 = xp[1], v2 = xp[2];
        float xa[12] = {v0.x, v0.y, v0.z, v0.w, v1.x, v1.y, v1.z, v1.w,
                        v2.x, v2.y, v2.z, v2.w};
        #pragma unroll
        for (int f = 0; f < 8; f++) {
            float a = 0.0f;
            #pragma unroll
            for (int c = 0; c < 12; c++) a += xa[c] * s_small[O_W1 + c * 8 + f];
            S1[n * S1S + f * 8 + b] = a;
        }
    }
    __syncthreads();

    // ========== A1: h1 = tanh(agg(t1)+b1); t2 = h1@W2 -> S2 ==========
    // warp per node; lane covers floats (2*lane, 2*lane+1) of the 64-float
    // row => f = lane>>2, b-pair = lane&3.
    {
        const int f  = lane >> 2;
        float w2r[4];
        #pragma unroll
        for (int f2 = 0; f2 < 4; f2++) w2r[f2] = s_small[O_W2 + f * 4 + f2];
        const float b1v = s_small[O_B1 + f];

        for (int n = wid; n < NN; n += NWARP) {
            const int j0 = s_rp[n], j1 = s_rp[n + 1];
            float2 acc = make_float2(b1v, b1v);
            float2 e = s_e[j0];
            for (int j = j0; j < j1; j++) {
                const float w = e.x;
                const int   s = __float_as_int(e.y);
                if (j + 1 < j1) e = s_e[j + 1];
                const float2 v = *(const float2*)(S1 + s * S1S + lane * 2);
                acc.x += w * v.x;
                acc.y += w * v.y;
            }
            float2 t;
            t.x = fast_tanh(acc.x);
            t.y = fast_tanh(acc.y);
            float2 p0, p1, p2, p3;
            p0.x = w2r[0] * t.x; p0.y = w2r[0] * t.y;
            p1.x = w2r[1] * t.x; p1.y = w2r[1] * t.y;
            p2.x = w2r[2] * t.x; p2.y = w2r[2] * t.y;
            p3.x = w2r[3] * t.x; p3.y = w2r[3] * t.y;
            #pragma unroll
            for (int off = 4; off <= 16; off <<= 1) {
                p0.x += __shfl_xor_sync(~0u, p0.x, off);
                p0.y += __shfl_xor_sync(~0u, p0.y, off);
                p1.x += __shfl_xor_sync(~0u, p1.x, off);
                p1.y += __shfl_xor_sync(~0u, p1.y, off);
                p2.x += __shfl_xor_sync(~0u, p2.x, off);
                p2.y += __shfl_xor_sync(~0u, p2.y, off);
                p3.x += __shfl_xor_sync(~0u, p3.x, off);
                p3.y += __shfl_xor_sync(~0u, p3.y, off);
            }
            if (lane < 16) {
                const int f2 = lane >> 2, bq = lane & 3;
                float2 v = p0;
                if (f2 == 1) v = p1;
                else if (f2 == 2) v = p2;
                else if (f2 == 3) v = p3;
                *(float2*)(S2 + n * S2S + f2 * 8 + bq * 2) = v;
            }
        }
    }
    __syncthreads();

    // ========== A2: h2 = tanh(agg(t2)+b2); t3 = h2@W3 -> S1 (t3) =====
    // lane covers float lane of the 32-float row: f = lane>>3, b = lane&7
    {
        const int f = lane >> 3;
        const float w3c0 = s_small[O_W3 + f * 2 + 0];
        const float w3c1 = s_small[O_W3 + f * 2 + 1];
        const float b2v  = s_small[O_B2 + f];

        for (int n = wid; n < NN; n += NWARP) {
            const int j0 = s_rp[n], j1 = s_rp[n + 1];
            float acc = 0.0f;
            float2 e = s_e[j0];
            for (int j = j0; j < j1; j++) {
                const float w = e.x;
                const int   s = __float_as_int(e.y);
                if (j + 1 < j1) e = s_e[j + 1];
                acc += w * S2[s * S2S + lane];
            }
            const float t = fast_tanh(acc + b2v);
            float p0 = w3c0 * t;
            float p1 = w3c1 * t;
            p0 += __shfl_xor_sync(~0u, p0, 8);
            p0 += __shfl_xor_sync(~0u, p0, 16);
            p1 += __shfl_xor_sync(~0u, p1, 8);
            p1 += __shfl_xor_sync(~0u, p1, 16);
            if (lane < 16) {
                const int c = lane >> 3, b = lane & 7;
                S1[n * T3S + c * 8 + b] = (c == 0) ? p0 : p1;
            }
        }
    }
    __syncthreads();

    // ========== A3: h3 = agg(t3)+b3 -> xfc[b][2n+c] in S2 ============
    {
        const int c = (lane >> 3) & 1, b = lane & 7;
        const float b3v = s_small[O_B3 + c];
        const int li = lane & 15;
        for (int n = wid; n < NN; n += NWARP) {
            const int j0 = s_rp[n], j1 = s_rp[n + 1];
            float acc = b3v;
            float2 e = s_e[j0];
            for (int j = j0; j < j1; j++) {
                const float w = e.x;
                const int   s = __float_as_int(e.y);
                if (j + 1 < j1) e = s_e[j + 1];
                acc += w * S1[s * T3S + li];
            }
            if (lane < 16)
                S2[b * XFS + 2 * n + c] = acc;
        }
    }
    __syncthreads();

    // ========== FC1: xfc[8,462] @ Wf1[462,120] + bf1 -> elu -> S1t ===
    if (tid < 240) {
        const int b = tid & 7, jg = tid >> 3;   // jg 0..29
        const int j0 = jg * 4;
        float4 acc = make_float4(s_small[O_BF1 + j0 + 0], s_small[O_BF1 + j0 + 1],
                                 s_small[O_BF1 + j0 + 2], s_small[O_BF1 + j0 + 3]);
        const float* xin = S2 + b * XFS;
        const float* wb  = Wf1 + j0;
        #pragma unroll 1
        for (int k = 0; k < 460; k += 4) {
            const float4 v  = *(const float4*)(xin + k);
            const float4 w0 = __ldg((const float4*)(wb + (k + 0) * 120));
            const float4 w1 = __ldg((const float4*)(wb + (k + 1) * 120));
            const float4 w2 = __ldg((const float4*)(wb + (k + 2) * 120));
            const float4 w3 = __ldg((const float4*)(wb + (k + 3) * 120));
            acc.x += v.x * w0.x + v.y * w1.x + v.z * w2.x + v.w * w3.x;
            acc.y += v.x * w0.y + v.y * w1.y + v.z * w2.y + v.w * w3.y;
            acc.z += v.x * w0.z + v.y * w1.z + v.z * w2.z + v.w * w3.z;
            acc.w += v.x * w0.w + v.y * w1.w + v.z * w2.w + v.w * w3.w;
        }
        #pragma unroll
        for (int k = 460; k < 462; k++) {
            const float v = xin[k];
            const float4 w0 = __ldg((const float4*)(wb + k * 120));
            acc.x += v * w0.x; acc.y += v * w0.y;
            acc.z += v * w0.z; acc.w += v * w0.w;
        }
        float4 r;
        r.x = elu1(acc.x); r.y = elu1(acc.y);
        r.z = elu1(acc.z); r.w = elu1(acc.w);
        *(float4*)(S1 + b * H1S + j0) = r;
    }
    __syncthreads();

    // ========== FC2: h1[8,120] @ Wf2[120,84] + bf2 -> elu -> S2t =====
    if (tid < 336) {
        const int b = tid & 7, jg = tid >> 3;   // jg 0..41
        const int j0 = jg * 2;
        float2 acc = make_float2(s_small[O_BF2 + j0], s_small[O_BF2 + j0 + 1]);
        const float* xin = S1 + b * H1S;
        const float* wb  = Wf2 + j0;
        #pragma unroll 2
        for (int k = 0; k < 120; k += 4) {
            const float4 v  = *(const float4*)(xin + k);
            const float2 w0 = __ldg((const float2*)(wb + (k + 0) * 84));
            const float2 w1 = __ldg((const float2*)(wb + (k + 1) * 84));
            const float2 w2 = __ldg((const float2*)(wb + (k + 2) * 84));
            const float2 w3 = __ldg((const float2*)(wb + (k + 3) * 84));
            acc.x += v.x * w0.x + v.y * w1.x + v.z * w2.x + v.w * w3.x;
            acc.y += v.x * w0.y + v.y * w1.y + v.z * w2.y + v.w * w3.y;
        }
        S2[b * H2S + j0 + 0] = elu1(acc.x);
        S2[b * H2S + j0 + 1] = elu1(acc.y);
    }
    __syncthreads();

    // ========== FC3: h2[8,84] @ Wf3[84,10] + bf3 -> out ==============
    if (tid < 80) {
        const int b = tid & 7, j = tid >> 3;    // j 0..9
        float acc = s_small[O_BF3 + j];
        const float* xin = S2 + b * H2S;
        #pragma unroll 3
        for (int k = 0; k < 84; k += 4) {
            const float4 v = *(const float4*)(xin + k);
            acc += v.x * __ldg(Wf3 + (k + 0) * 10 + j);
            acc += v.y * __ldg(Wf3 + (k + 1) * 10 + j);
            acc += v.z * __ldg(Wf3 + (k + 2) * 10 + j);
            acc += v.w * __ldg(Wf3 + (k + 3) * 10 + j);
        }
        out[(size_t)(b0 + b) * 10 + j] = acc;
    }
}

// =====================================================================
extern "C" void kernel_launch(void* const* d_in, const int* in_sizes, int n_in,
                              void* d_out, int out_size) {
    const float* x   = (const float*)d_in[0];
    const void*  ei  = d_in[1];
    const float* W1  = (const float*)d_in[2];
    const float* b1  = (const float*)d_in[3];
    const float* W2  = (const float*)d_in[4];
    const float* b2  = (const float*)d_in[5];
    const float* W3  = (const float*)d_in[6];
    const float* b3  = (const float*)d_in[7];
    const float* Wf1 = (const float*)d_in[8];
    const float* bf1 = (const float*)d_in[9];
    const float* Wf2 = (const float*)d_in[10];
    const float* bf2 = (const float*)d_in[11];
    const float* Wf3 = (const float*)d_in[12];
    const float* bf3 = (const float*)d_in[13];
    float* out = (float*)d_out;

    const int B = in_sizes[0] / (NN * 12);
    const int E = in_sizes[1] / 2;
    const int M = E + NN;

    prep_kernel<<<1, 256>>>(ei, E);

    static int smem_set = 0;
    if (!smem_set) {
        cudaFuncSetAttribute(gcn_fused_kernel,
                             cudaFuncAttributeMaxDynamicSharedMemorySize,
                             SM_BYTES);
        smem_set = 1;
    }

    const int blocks = (B + BT - 1) / BT;
    gcn_fused_kernel<<<blocks, THREADS, SM_BYTES>>>(
        x, W1, b1, W2, b2, W3, b3, Wf1, bf1, Wf2, bf2, Wf3, bf3,
        out, B, M);
}

// round 6
// speedup vs baseline: 1.1372x; 1.1372x over previous
#include <cuda_runtime.h>
#include <math.h>

#define NN 231
#define BT 8
#define THREADS 512
#define NWARP 16
#define MAXM 4096
#define CAP  2368     // padded-even edge capacity (actual <= 2310)

#define S1S 64    // t1 row: [b=8][f=8] contiguous
#define S2S 32    // t2 row: [b=8][f=4]
#define T3S 16    // t3 row: [b=8][c=2]
#define XFS 476   // FC input stride per graph
#define H1S 124   // FC1 out stride
#define H2S 92    // FC2 out stride

// ---------------- persistent CSR built by prep kernel ----------------
__device__ int   g_row_ptr[NN + 1];
__device__ int   g_csr_src[MAXM];
__device__ float g_csr_w[MAXM];

// =====================================================================
// Prep: deterministic CSR (stable counting sort by dst), rows padded to
// EVEN length with (src=0, w=0) dummies; tail zero-filled to CAP.
// =====================================================================
__global__ void prep_kernel(const void* __restrict__ ei, int E) {
    __shared__ short s_src[2304];
    __shared__ short s_dst[2304];
    __shared__ int   deg[NN];
    __shared__ int   pdeg[NN];
    __shared__ int   rp[NN + 1];
    __shared__ float inv[NN];
    __shared__ int   cnt[32][NN];
    __shared__ int   is64;

    const int tid = threadIdx.x;
    const int M = E + NN;

    if (tid == 0) {
        const long long* p = (const long long*)ei;
        int ok = 1;
        for (int i = 0; i < 8; i++) {
            long long v = p[i];
            if (v < 0 || v >= NN) ok = 0;
        }
        is64 = ok;
    }
    for (int n = tid; n < NN; n += blockDim.x) deg[n] = 0;
    __syncthreads();

    for (int e = tid; e < M; e += blockDim.x) {
        int s, d;
        if (e < E) {
            if (is64) {
                s = (int)((const long long*)ei)[e];
                d = (int)((const long long*)ei)[E + e];
            } else {
                s = ((const int*)ei)[e];
                d = ((const int*)ei)[E + e];
            }
        } else {
            s = d = e - E;
        }
        s_src[e] = (short)s;
        s_dst[e] = (short)d;
        atomicAdd(&deg[d], 1);
    }
    __syncthreads();

    for (int n = tid; n < NN; n += blockDim.x) {
        inv[n]  = rsqrtf((float)max(deg[n], 1));
        pdeg[n] = (deg[n] + 1) & ~1;
    }
    __syncthreads();
    if (tid == 0) {
        int acc = 0;
        for (int n = 0; n < NN; n++) { rp[n] = acc; acc += pdeg[n]; }
        rp[NN] = acc;
    }
    for (int i = tid; i < 32 * NN; i += blockDim.x)
        ((int*)cnt)[i] = 0;
    __syncthreads();

    const int chunk = (M + 31) / 32;
    if (tid < 32) {
        int e0 = tid * chunk, e1 = min(e0 + chunk, M);
        for (int e = e0; e < e1; e++) cnt[tid][s_dst[e]]++;
    }
    __syncthreads();

    for (int n = tid; n < NN; n += blockDim.x) {
        int run = rp[n];
        for (int t = 0; t < 32; t++) {
            int c = cnt[t][n];
            cnt[t][n] = run;
            run += c;
        }
    }
    __syncthreads();

    if (tid < 32) {
        int e0 = tid * chunk, e1 = min(e0 + chunk, M);
        for (int e = e0; e < e1; e++) {
            int d = s_dst[e], s = s_src[e];
            int pos = cnt[tid][d]++;
            g_csr_src[pos] = s;
            g_csr_w[pos]   = inv[s] * inv[d];
        }
    }
    __syncthreads();

    // pad odd rows with one dummy edge
    for (int n = tid; n < NN; n += blockDim.x) {
        if (deg[n] < pdeg[n]) {
            int pos = rp[n] + deg[n];
            g_csr_src[pos] = 0;
            g_csr_w[pos]   = 0.0f;
        }
    }
    // zero tail up to CAP
    for (int i = rp[NN] + tid; i < CAP; i += blockDim.x) {
        g_csr_src[i] = 0;
        g_csr_w[i]   = 0.0f;
    }
    for (int n = tid; n <= NN; n += blockDim.x) g_row_ptr[n] = rp[n];
}

// =====================================================================
__device__ __forceinline__ float htanh(float x) {
    float y;
    asm("tanh.approx.f32 %0, %1;" : "=f"(y) : "f"(x));
    return y;
}
__device__ __forceinline__ float elu1(float v) {
    return v > 0.0f ? v : (__expf(v) - 1.0f);
}

// small-weight shared offsets (floats)
#define O_W1  0      // 12x8
#define O_B1  96     // 8
#define O_W2  104    // 8x4
#define O_B2  136    // 4
#define O_W3  140    // 4x2
#define O_B3  148    // 2
#define O_BF1 152    // 120
#define O_BF2 272    // 84
#define O_BF3 356    // 10
#define SMALLSZ 384

// smem floats: S1 + S2 + s_e(float2) + small, then rp ints
#define SM_FLOATS (NN*S1S + NN*S2S + 2*CAP + SMALLSZ)
#define SM_BYTES  (SM_FLOATS*4 + (NN+1)*4)

__global__ void __launch_bounds__(THREADS, 2)
gcn_fused_kernel(const float* __restrict__ x,
                 const float* __restrict__ W1, const float* __restrict__ b1,
                 const float* __restrict__ W2, const float* __restrict__ b2,
                 const float* __restrict__ W3, const float* __restrict__ b3,
                 const float* __restrict__ Wf1, const float* __restrict__ bf1,
                 const float* __restrict__ Wf2, const float* __restrict__ bf2,
                 const float* __restrict__ Wf3, const float* __restrict__ bf3,
                 float* __restrict__ out, int B) {
    extern __shared__ float sm[];
    float*  S1      = sm;                        // t1 [n][b][f] 64/row
    float*  S2      = S1 + NN * S1S;             // t2 [n][b][f] 32/row
    float2* s_e     = (float2*)(S2 + NN * S2S);  // (w, src-bits), CAP entries
    float*  s_small = (float*)(s_e + CAP);
    int*    s_rp    = (int*)(s_small + SMALLSZ);

    const int tid  = threadIdx.x;
    const int wid  = tid >> 5;
    const int lane = tid & 31;
    const int b0   = blockIdx.x * BT;

    // ---- stage CSR + small weights ----
    for (int i = tid; i <= NN; i += THREADS) s_rp[i] = g_row_ptr[i];
    for (int i = tid; i < CAP; i += THREADS)
        s_e[i] = make_float2(g_csr_w[i], __int_as_float(g_csr_src[i]));
    for (int i = tid; i < 96;  i += THREADS) s_small[O_W1 + i] = W1[i];
    for (int i = tid; i < 8;   i += THREADS) s_small[O_B1 + i] = b1[i];
    for (int i = tid; i < 32;  i += THREADS) s_small[O_W2 + i] = W2[i];
    for (int i = tid; i < 4;   i += THREADS) s_small[O_B2 + i] = b2[i];
    for (int i = tid; i < 8;   i += THREADS) s_small[O_W3 + i] = W3[i];
    for (int i = tid; i < 2;   i += THREADS) s_small[O_B3 + i] = b3[i];
    for (int i = tid; i < 120; i += THREADS) s_small[O_BF1 + i] = bf1[i];
    for (int i = tid; i < 84;  i += THREADS) s_small[O_BF2 + i] = bf2[i];
    for (int i = tid; i < 10;  i += THREADS) s_small[O_BF3 + i] = bf3[i];
    __syncthreads();

    // ========== T1: t1 = x @ W1 -> S1[n][b][f] ==========
    for (int idx = tid; idx < NN * BT; idx += THREADS) {
        const int b = idx / NN, n = idx - b * NN;
        const int g = b0 + b;
        const float4* xp = (const float4*)(x + ((size_t)g * NN + n) * 12);
        float4 v0 = xp[0], v1 = xp[1], v2 = xp[2];
        float xa[12] = {v0.x, v0.y, v0.z, v0.w, v1.x, v1.y, v1.z, v1.w,
                        v2.x, v2.y, v2.z, v2.w};
        float4 r0, r1;
        {
            float t[8];
            #pragma unroll
            for (int f = 0; f < 8; f++) {
                float a = 0.0f;
                #pragma unroll
                for (int c = 0; c < 12; c++) a += xa[c] * s_small[O_W1 + c * 8 + f];
                t[f] = a;
            }
            r0 = make_float4(t[0], t[1], t[2], t[3]);
            r1 = make_float4(t[4], t[5], t[6], t[7]);
        }
        float* dst = S1 + n * S1S + b * 8;
        *(float4*)dst       = r0;
        *(float4*)(dst + 4) = r1;
    }
    __syncthreads();

    // ========== A1: h1 = tanh(agg(t1)+b1); t2 = h1@W2 -> S2 ==========
    // warp per node; lane l owns (b = l>>2, f = 2*(l&3), 2*(l&3)+1)
    {
        const int fp = (lane & 3) * 2;
        float w2a[4], w2b[4];
        #pragma unroll
        for (int f2 = 0; f2 < 4; f2++) {
            w2a[f2] = s_small[O_W2 + fp * 4 + f2];
            w2b[f2] = s_small[O_W2 + (fp + 1) * 4 + f2];
        }
        const float b1x = s_small[O_B1 + fp];
        const float b1y = s_small[O_B1 + fp + 1];
        const int off2 = lane * 2;

        for (int n = wid; n < NN; n += NWARP) {
            const int j0 = s_rp[n], j1 = s_rp[n + 1];
            float ax = 0.0f, ay = 0.0f;
            for (int j = j0; j < j1; j += 2) {
                const float2 e0 = s_e[j];
                const float2 e1 = s_e[j + 1];
                const float2 v0 = *(const float2*)(S1 + __float_as_int(e0.y) * S1S + off2);
                const float2 v1 = *(const float2*)(S1 + __float_as_int(e1.y) * S1S + off2);
                ax += e0.x * v0.x + e1.x * v1.x;
                ay += e0.x * v0.y + e1.x * v1.y;
            }
            const float tx = htanh(ax + b1x);
            const float ty = htanh(ay + b1y);
            float p0 = tx * w2a[0] + ty * w2b[0];
            float p1 = tx * w2a[1] + ty * w2b[1];
            float p2 = tx * w2a[2] + ty * w2b[2];
            float p3 = tx * w2a[3] + ty * w2b[3];
            #pragma unroll
            for (int off = 1; off <= 2; off <<= 1) {
                p0 += __shfl_xor_sync(~0u, p0, off);
                p1 += __shfl_xor_sync(~0u, p1, off);
                p2 += __shfl_xor_sync(~0u, p2, off);
                p3 += __shfl_xor_sync(~0u, p3, off);
            }
            const int q = lane & 3;
            float v = (q == 0) ? p0 : (q == 1) ? p1 : (q == 2) ? p2 : p3;
            S2[n * S2S + lane] = v;   // [n][b][f2]: b*4+q == lane
        }
    }
    __syncthreads();

    // ========== A2: h2 = tanh(agg(t2)+b2); t3 = h2@W3 -> S1 (t3) =====
    // lane l owns (b = l>>2, f = l&3)
    {
        const int f = lane & 3;
        const float w3c0 = s_small[O_W3 + f * 2 + 0];
        const float w3c1 = s_small[O_W3 + f * 2 + 1];
        const float b2v  = s_small[O_B2 + f];

        for (int n = wid; n < NN; n += NWARP) {
            const int j0 = s_rp[n], j1 = s_rp[n + 1];
            float acc = 0.0f;
            for (int j = j0; j < j1; j += 2) {
                const float2 e0 = s_e[j];
                const float2 e1 = s_e[j + 1];
                acc += e0.x * S2[__float_as_int(e0.y) * S2S + lane]
                     + e1.x * S2[__float_as_int(e1.y) * S2S + lane];
            }
            const float t = htanh(acc + b2v);
            float p0 = t * w3c0;
            float p1 = t * w3c1;
            #pragma unroll
            for (int off = 1; off <= 2; off <<= 1) {
                p0 += __shfl_xor_sync(~0u, p0, off);
                p1 += __shfl_xor_sync(~0u, p1, off);
            }
            const int q = lane & 3;
            if (q < 2)
                S1[n * T3S + (lane >> 2) * 2 + q] = (q == 0) ? p0 : p1;
        }
    }
    __syncthreads();

    // ========== A3: h3 = agg(t3)+b3 -> xfc[b][2n+c] in S2 ============
    {
        const int li = lane & 15;        // t3 row float index
        const int b = li >> 1, c = li & 1;
        const float b3v = s_small[O_B3 + c];
        for (int n = wid; n < NN; n += NWARP) {
            const int j0 = s_rp[n], j1 = s_rp[n + 1];
            float acc = b3v;
            for (int j = j0; j < j1; j += 2) {
                const float2 e0 = s_e[j];
                const float2 e1 = s_e[j + 1];
                acc += e0.x * S1[__float_as_int(e0.y) * T3S + li]
                     + e1.x * S1[__float_as_int(e1.y) * T3S + li];
            }
            if (lane < 16)
                S2[b * XFS + 2 * n + c] = acc;
        }
    }
    __syncthreads();

    // ========== FC1: xfc[8,462] @ Wf1[462,120] + bf1 -> elu -> S1 ====
    if (tid < 480) {
        const int b = tid & 7, jg = tid >> 3;   // jg 0..59
        const int j0 = jg * 2;
        float2 acc = make_float2(s_small[O_BF1 + j0], s_small[O_BF1 + j0 + 1]);
        const float* xin = S2 + b * XFS;
        const float* wb  = Wf1 + j0;
        #pragma unroll 1
        for (int k = 0; k < 460; k += 4) {
            const float4 v  = *(const float4*)(xin + k);
            const float2 w0 = __ldg((const float2*)(wb + (k + 0) * 120));
            const float2 w1 = __ldg((const float2*)(wb + (k + 1) * 120));
            const float2 w2 = __ldg((const float2*)(wb + (k + 2) * 120));
            const float2 w3 = __ldg((const float2*)(wb + (k + 3) * 120));
            acc.x += v.x * w0.x + v.y * w1.x + v.z * w2.x + v.w * w3.x;
            acc.y += v.x * w0.y + v.y * w1.y + v.z * w2.y + v.w * w3.y;
        }
        {
            const float2 v  = *(const float2*)(xin + 460);
            const float2 w0 = __ldg((const float2*)(wb + 460 * 120));
            const float2 w1 = __ldg((const float2*)(wb + 461 * 120));
            acc.x += v.x * w0.x + v.y * w1.x;
            acc.y += v.x * w0.y + v.y * w1.y;
        }
        S1[b * H1S + j0 + 0] = elu1(acc.x);
        S1[b * H1S + j0 + 1] = elu1(acc.y);
    }
    __syncthreads();

    // ========== FC2: h1[8,120] @ Wf2[120,84] + bf2 -> elu -> S2 ======
    if (tid < 336) {
        const int b = tid & 7, jg = tid >> 3;   // jg 0..41
        const int j0 = jg * 2;
        float2 acc = make_float2(s_small[O_BF2 + j0], s_small[O_BF2 + j0 + 1]);
        const float* xin = S1 + b * H1S;
        const float* wb  = Wf2 + j0;
        #pragma unroll 2
        for (int k = 0; k < 120; k += 4) {
            const float4 v  = *(const float4*)(xin + k);
            const float2 w0 = __ldg((const float2*)(wb + (k + 0) * 84));
            const float2 w1 = __ldg((const float2*)(wb + (k + 1) * 84));
            const float2 w2 = __ldg((const float2*)(wb + (k + 2) * 84));
            const float2 w3 = __ldg((const float2*)(wb + (k + 3) * 84));
            acc.x += v.x * w0.x + v.y * w1.x + v.z * w2.x + v.w * w3.x;
            acc.y += v.x * w0.y + v.y * w1.y + v.z * w2.y + v.w * w3.y;
        }
        S2[b * H2S + j0 + 0] = elu1(acc.x);
        S2[b * H2S + j0 + 1] = elu1(acc.y);
    }
    __syncthreads();

    // ========== FC3: h2[8,84] @ Wf3[84,10] + bf3 -> out ==============
    if (tid < 80) {
        const int b = tid & 7, j = tid >> 3;    // j 0..9
        float acc = s_small[O_BF3 + j];
        const float* xin = S2 + b * H2S;
        #pragma unroll 3
        for (int k = 0; k < 84; k += 4) {
            const float4 v = *(const float4*)(xin + k);
            acc += v.x * __ldg(Wf3 + (k + 0) * 10 + j);
            acc += v.y * __ldg(Wf3 + (k + 1) * 10 + j);
            acc += v.z * __ldg(Wf3 + (k + 2) * 10 + j);
            acc += v.w * __ldg(Wf3 + (k + 3) * 10 + j);
        }
        out[(size_t)(b0 + b) * 10 + j] = acc;
    }
}

// =====================================================================
extern "C" void kernel_launch(void* const* d_in, const int* in_sizes, int n_in,
                              void* d_out, int out_size) {
    const float* x   = (const float*)d_in[0];
    const void*  ei  = d_in[1];
    const float* W1  = (const float*)d_in[2];
    const float* b1  = (const float*)d_in[3];
    const float* W2  = (const float*)d_in[4];
    const float* b2  = (const float*)d_in[5];
    const float* W3  = (const float*)d_in[6];
    const float* b3  = (const float*)d_in[7];
    const float* Wf1 = (const float*)d_in[8];
    const float* bf1 = (const float*)d_in[9];
    const float* Wf2 = (const float*)d_in[10];
    const float* bf2 = (const float*)d_in[11];
    const float* Wf3 = (const float*)d_in[12];
    const float* bf3 = (const float*)d_in[13];
    float* out = (float*)d_out;

    const int B = in_sizes[0] / (NN * 12);
    const int E = in_sizes[1] / 2;

    prep_kernel<<<1, 256>>>(ei, E);

    static int smem_set = 0;
    if (!smem_set) {
        cudaFuncSetAttribute(gcn_fused_kernel,
                             cudaFuncAttributeMaxDynamicSharedMemorySize,
                             SM_BYTES);
        smem_set = 1;
    }

    const int blocks = (B + BT - 1) / BT;
    gcn_fused_kernel<<<blocks, THREADS, SM_BYTES>>>(
        x, W1, b1, W2, b2, W3, b3, Wf1, bf1, Wf2, bf2, Wf3, bf3,
        out, B);
}

// round 7
// speedup vs baseline: 1.4129x; 1.2424x over previous
#include <cuda_runtime.h>
#include <math.h>

#define NN 231
#define BT 8
#define THREADS 512
#define NWARP 16
#define MAXM 4096     // padded-to-4 edges <= 231*4 + 2079 ~ 3003

#define S1S 68    // t1 row stride: 64 data + 4 (bank rotate, 16B aligned)
#define S2S 36    // t2 row stride: 32 + 4
#define T3S 20    // t3 row stride: 16 + 4
#define XFS 476   // FC input stride per graph
#define H1S 124   // FC1 out stride
#define H2S 92    // FC2 out stride

// ---------------- persistent CSR built by prep kernel ----------------
__device__ int    g_row_ptr[NN + 1];
__device__ float2 g_csr_e[MAXM];    // (w, src-as-float-bits)

// =====================================================================
// Prep: deterministic CSR (stable counting sort by dst); each row padded
// to a multiple of 4 with (w=0, src=0) dummies.
// =====================================================================
__global__ void prep_kernel(const void* __restrict__ ei, int E) {
    __shared__ short s_src[2304];
    __shared__ short s_dst[2304];
    __shared__ int   deg[NN];
    __shared__ int   pdeg[NN];
    __shared__ int   rp[NN + 1];
    __shared__ float inv[NN];
    __shared__ int   cnt[32][NN];
    __shared__ int   is64;

    const int tid = threadIdx.x;
    const int M = E + NN;

    if (tid == 0) {
        const long long* p = (const long long*)ei;
        int ok = 1;
        for (int i = 0; i < 8; i++) {
            long long v = p[i];
            if (v < 0 || v >= NN) ok = 0;
        }
        is64 = ok;
    }
    for (int n = tid; n < NN; n += blockDim.x) deg[n] = 0;
    __syncthreads();

    for (int e = tid; e < M; e += blockDim.x) {
        int s, d;
        if (e < E) {
            if (is64) {
                s = (int)((const long long*)ei)[e];
                d = (int)((const long long*)ei)[E + e];
            } else {
                s = ((const int*)ei)[e];
                d = ((const int*)ei)[E + e];
            }
        } else {
            s = d = e - E;   // self loops appended after real edges
        }
        s_src[e] = (short)s;
        s_dst[e] = (short)d;
        atomicAdd(&deg[d], 1);
    }
    __syncthreads();

    for (int n = tid; n < NN; n += blockDim.x) {
        inv[n]  = rsqrtf((float)max(deg[n], 1));
        pdeg[n] = (deg[n] + 3) & ~3;
    }
    __syncthreads();
    if (tid == 0) {
        int acc = 0;
        for (int n = 0; n < NN; n++) { rp[n] = acc; acc += pdeg[n]; }
        rp[NN] = acc;
    }
    for (int i = tid; i < 32 * NN; i += blockDim.x)
        ((int*)cnt)[i] = 0;
    __syncthreads();

    const int chunk = (M + 31) / 32;
    if (tid < 32) {
        int e0 = tid * chunk, e1 = min(e0 + chunk, M);
        for (int e = e0; e < e1; e++) cnt[tid][s_dst[e]]++;
    }
    __syncthreads();

    for (int n = tid; n < NN; n += blockDim.x) {
        int run = rp[n];
        for (int t = 0; t < 32; t++) {
            int c = cnt[t][n];
            cnt[t][n] = run;
            run += c;
        }
    }
    __syncthreads();

    if (tid < 32) {
        int e0 = tid * chunk, e1 = min(e0 + chunk, M);
        for (int e = e0; e < e1; e++) {
            int d = s_dst[e], s = s_src[e];
            int pos = cnt[tid][d]++;
            g_csr_e[pos] = make_float2(inv[s] * inv[d], __int_as_float(s));
        }
    }
    __syncthreads();

    // pad rows with dummy edges (w=0, src=0)
    for (int n = tid; n < NN; n += blockDim.x) {
        for (int p = deg[n]; p < pdeg[n]; p++)
            g_csr_e[rp[n] + p] = make_float2(0.0f, __int_as_float(0));
    }
    for (int n = tid; n <= NN; n += blockDim.x) g_row_ptr[n] = rp[n];
}

// =====================================================================
__device__ __forceinline__ float htanh(float x) {
    float y;
    asm("tanh.approx.f32 %0, %1;" : "=f"(y) : "f"(x));
    return y;
}
__device__ __forceinline__ float elu1(float v) {
    return v > 0.0f ? v : (__expf(v) - 1.0f);
}

// small-weight shared offsets (floats)
#define O_W1  0      // 12x8
#define O_B1  96     // 8
#define O_W2  104    // 8x4
#define O_B2  136    // 4
#define O_W3  140    // 4x2
#define O_B3  148    // 2
#define O_BF1 152    // 120
#define O_BF2 272    // 84
#define O_BF3 356    // 10
#define SMALLSZ 384

#define SM_FLOATS (NN*S1S + NN*S2S + SMALLSZ)
#define SM_BYTES  (SM_FLOATS*4 + (NN+1)*4)

__global__ void __launch_bounds__(THREADS, 2)
gcn_fused_kernel(const float* __restrict__ x,
                 const float* __restrict__ W1, const float* __restrict__ b1,
                 const float* __restrict__ W2, const float* __restrict__ b2,
                 const float* __restrict__ W3, const float* __restrict__ b3,
                 const float* __restrict__ Wf1, const float* __restrict__ bf1,
                 const float* __restrict__ Wf2, const float* __restrict__ bf2,
                 const float* __restrict__ Wf3, const float* __restrict__ bf3,
                 float* __restrict__ out, int B) {
    extern __shared__ float sm[];
    float*  S1      = sm;                  // t1 [n][b8][f8], stride 68
    float*  S2      = S1 + NN * S1S;       // t2 [n][b8][f4], stride 36
    float*  s_small = S2 + NN * S2S;
    int*    s_rp    = (int*)(s_small + SMALLSZ);

    const int tid  = threadIdx.x;
    const int wid  = tid >> 5;
    const int lane = tid & 31;
    const int b0   = blockIdx.x * BT;

    // ---- stage rp + small weights ----
    for (int i = tid; i <= NN; i += THREADS) s_rp[i] = g_row_ptr[i];
    for (int i = tid; i < 96;  i += THREADS) s_small[O_W1 + i] = W1[i];
    for (int i = tid; i < 8;   i += THREADS) s_small[O_B1 + i] = b1[i];
    for (int i = tid; i < 32;  i += THREADS) s_small[O_W2 + i] = W2[i];
    for (int i = tid; i < 4;   i += THREADS) s_small[O_B2 + i] = b2[i];
    for (int i = tid; i < 8;   i += THREADS) s_small[O_W3 + i] = W3[i];
    for (int i = tid; i < 2;   i += THREADS) s_small[O_B3 + i] = b3[i];
    for (int i = tid; i < 120; i += THREADS) s_small[O_BF1 + i] = bf1[i];
    for (int i = tid; i < 84;  i += THREADS) s_small[O_BF2 + i] = bf2[i];
    for (int i = tid; i < 10;  i += THREADS) s_small[O_BF3 + i] = bf3[i];
    __syncthreads();

    // ========== T1: t1 = x @ W1 -> S1[n][b][f] ==========
    for (int idx = tid; idx < NN * BT; idx += THREADS) {
        const int b = idx / NN, n = idx - b * NN;
        const int g = b0 + b;
        float xa[12];
        if (g < B) {
            const float4* xp = (const float4*)(x + ((size_t)g * NN + n) * 12);
            float4 v0 = xp[0], v1 = xp[1], v2 = xp[2];
            xa[0] = v0.x; xa[1] = v0.y; xa[2]  = v0.z; xa[3]  = v0.w;
            xa[4] = v1.x; xa[5] = v1.y; xa[6]  = v1.z; xa[7]  = v1.w;
            xa[8] = v2.x; xa[9] = v2.y; xa[10] = v2.z; xa[11] = v2.w;
        } else {
            #pragma unroll
            for (int c = 0; c < 12; c++) xa[c] = 0.0f;
        }
        float t[8];
        #pragma unroll
        for (int f = 0; f < 8; f++) {
            float a = 0.0f;
            #pragma unroll
            for (int c = 0; c < 12; c++) a += xa[c] * s_small[O_W1 + c * 8 + f];
            t[f] = a;
        }
        float* dst = S1 + n * S1S + b * 8;
        *(float4*)dst       = make_float4(t[0], t[1], t[2], t[3]);
        *(float4*)(dst + 4) = make_float4(t[4], t[5], t[6], t[7]);
    }
    __syncthreads();

    // ========== A1: h1 = tanh(agg(t1)+b1); t2 = h1@W2 -> S2 ==========
    // half-warp per edge; lane: h = edge half, lh owns float4 of the
    // 64-float row: b = lh>>1, fq = (lh&1)*4.
    {
        const int h  = lane >> 4;
        const int lh = lane & 15;
        const int fq = (lh & 1) * 4;
        float w2r[4][4];
        #pragma unroll
        for (int i = 0; i < 4; i++)
            #pragma unroll
            for (int f2 = 0; f2 < 4; f2++)
                w2r[i][f2] = s_small[O_W2 + (fq + i) * 4 + f2];
        const float4 b1v = *(const float4*)(s_small + O_B1 + fq);

        for (int n = wid; n < NN; n += NWARP) {
            const int j0 = s_rp[n], j1 = s_rp[n + 1];
            float4 acc = make_float4(0.f, 0.f, 0.f, 0.f);
            for (int j = j0; j < j1; j += 2) {
                const float2 e = __ldg(&g_csr_e[j + h]);
                const float4 v = *(const float4*)(S1 + __float_as_int(e.y) * S1S + lh * 4);
                acc.x += e.x * v.x; acc.y += e.x * v.y;
                acc.z += e.x * v.z; acc.w += e.x * v.w;
            }
            acc.x += __shfl_xor_sync(~0u, acc.x, 16);
            acc.y += __shfl_xor_sync(~0u, acc.y, 16);
            acc.z += __shfl_xor_sync(~0u, acc.z, 16);
            acc.w += __shfl_xor_sync(~0u, acc.w, 16);
            const float tx = htanh(acc.x + b1v.x);
            const float ty = htanh(acc.y + b1v.y);
            const float tz = htanh(acc.z + b1v.z);
            const float tw = htanh(acc.w + b1v.w);
            float4 p;
            p.x = tx * w2r[0][0] + ty * w2r[1][0] + tz * w2r[2][0] + tw * w2r[3][0];
            p.y = tx * w2r[0][1] + ty * w2r[1][1] + tz * w2r[2][1] + tw * w2r[3][1];
            p.z = tx * w2r[0][2] + ty * w2r[1][2] + tz * w2r[2][2] + tw * w2r[3][2];
            p.w = tx * w2r[0][3] + ty * w2r[1][3] + tz * w2r[2][3] + tw * w2r[3][3];
            p.x += __shfl_xor_sync(~0u, p.x, 1);
            p.y += __shfl_xor_sync(~0u, p.y, 1);
            p.z += __shfl_xor_sync(~0u, p.z, 1);
            p.w += __shfl_xor_sync(~0u, p.w, 1);
            if (lane < 16 && !(lane & 1))
                *(float4*)(S2 + n * S2S + (lh >> 1) * 4) = p;
        }
    }
    __syncthreads();

    // ========== A2: h2 = tanh(agg(t2)+b2); t3 = h2@W3 -> S1 (t3) =====
    // quarter-warp per edge; lane: q = edge quarter, lb owns float4
    // (all 4 f of batch lb).
    {
        const int q  = lane >> 3;
        const int lb = lane & 7;
        const float4 b2v = *(const float4*)(s_small + O_B2);
        float w30[4], w31[4];
        #pragma unroll
        for (int f = 0; f < 4; f++) {
            w30[f] = s_small[O_W3 + f * 2 + 0];
            w31[f] = s_small[O_W3 + f * 2 + 1];
        }
        for (int n = wid; n < NN; n += NWARP) {
            const int j0 = s_rp[n], j1 = s_rp[n + 1];
            float4 acc = make_float4(0.f, 0.f, 0.f, 0.f);
            for (int j = j0; j < j1; j += 4) {
                const float2 e = __ldg(&g_csr_e[j + q]);
                const float4 v = *(const float4*)(S2 + __float_as_int(e.y) * S2S + lb * 4);
                acc.x += e.x * v.x; acc.y += e.x * v.y;
                acc.z += e.x * v.z; acc.w += e.x * v.w;
            }
            #pragma unroll
            for (int off = 8; off <= 16; off <<= 1) {
                acc.x += __shfl_xor_sync(~0u, acc.x, off);
                acc.y += __shfl_xor_sync(~0u, acc.y, off);
                acc.z += __shfl_xor_sync(~0u, acc.z, off);
                acc.w += __shfl_xor_sync(~0u, acc.w, off);
            }
            const float t0 = htanh(acc.x + b2v.x);
            const float t1 = htanh(acc.y + b2v.y);
            const float t2 = htanh(acc.z + b2v.z);
            const float t3 = htanh(acc.w + b2v.w);
            const float p0 = t0 * w30[0] + t1 * w30[1] + t2 * w30[2] + t3 * w30[3];
            const float p1 = t0 * w31[0] + t1 * w31[1] + t2 * w31[2] + t3 * w31[3];
            if (lane < 8)
                *(float2*)(S1 + n * T3S + lb * 2) = make_float2(p0, p1);
        }
    }
    __syncthreads();

    // ========== A3: h3 = agg(t3)+b3 -> xfc[b][2n+c] in S2 ============
    {
        const int o  = lane >> 3;
        const int lb = lane & 7;
        const float b3x = s_small[O_B3 + 0];
        const float b3y = s_small[O_B3 + 1];
        for (int n = wid; n < NN; n += NWARP) {
            const int j0 = s_rp[n], j1 = s_rp[n + 1];
            float ax = 0.0f, ay = 0.0f;
            for (int j = j0; j < j1; j += 4) {
                const float2 e = __ldg(&g_csr_e[j + o]);
                const float2 v = *(const float2*)(S1 + __float_as_int(e.y) * T3S + lb * 2);
                ax += e.x * v.x;
                ay += e.x * v.y;
            }
            #pragma unroll
            for (int off = 8; off <= 16; off <<= 1) {
                ax += __shfl_xor_sync(~0u, ax, off);
                ay += __shfl_xor_sync(~0u, ay, off);
            }
            if (lane < 8)
                *(float2*)(S2 + lb * XFS + 2 * n) = make_float2(ax + b3x, ay + b3y);
        }
    }
    __syncthreads();

    // ========== FC1: xfc[8,462] @ Wf1[462,120] + bf1 -> elu -> S1 ====
    // thread = (jg<60: 2 j's, bq: 4 b's, kh: k half). 240 active.
    {
        const int jg = tid & 63;
        const int bq = (tid >> 6) & 1;
        const int kh = tid >> 7;
        const bool active = (tid < 256) && (jg < 60);
        float acc[2][4];
        #pragma unroll
        for (int j = 0; j < 2; j++)
            #pragma unroll
            for (int i = 0; i < 4; i++) acc[j][i] = 0.0f;

        if (active) {
            const int j0 = jg * 2;
            const float* wb = Wf1 + j0;
            const float* x0 = S2 + (bq * 4 + 0) * XFS;
            const float* x1 = S2 + (bq * 4 + 1) * XFS;
            const float* x2 = S2 + (bq * 4 + 2) * XFS;
            const float* x3 = S2 + (bq * 4 + 3) * XFS;
            const int k0 = kh ? 232 : 0;
            const int k1 = kh ? 460 : 232;
            for (int k = k0; k < k1; k += 4) {
                const float4 a0 = *(const float4*)(x0 + k);
                const float4 a1 = *(const float4*)(x1 + k);
                const float4 a2 = *(const float4*)(x2 + k);
                const float4 a3 = *(const float4*)(x3 + k);
                const float2 w0 = __ldg((const float2*)(wb + (k + 0) * 120));
                const float2 w1 = __ldg((const float2*)(wb + (k + 1) * 120));
                const float2 w2 = __ldg((const float2*)(wb + (k + 2) * 120));
                const float2 w3 = __ldg((const float2*)(wb + (k + 3) * 120));
                acc[0][0] += a0.x * w0.x + a0.y * w1.x + a0.z * w2.x + a0.w * w3.x;
                acc[1][0] += a0.x * w0.y + a0.y * w1.y + a0.z * w2.y + a0.w * w3.y;
                acc[0][1] += a1.x * w0.x + a1.y * w1.x + a1.z * w2.x + a1.w * w3.x;
                acc[1][1] += a1.x * w0.y + a1.y * w1.y + a1.z * w2.y + a1.w * w3.y;
                acc[0][2] += a2.x * w0.x + a2.y * w1.x + a2.z * w2.x + a2.w * w3.x;
                acc[1][2] += a2.x * w0.y + a2.y * w1.y + a2.z * w2.y + a2.w * w3.y;
                acc[0][3] += a3.x * w0.x + a3.y * w1.x + a3.z * w2.x + a3.w * w3.x;
                acc[1][3] += a3.x * w0.y + a3.y * w1.y + a3.z * w2.y + a3.w * w3.y;
            }
            if (kh) {   // tail k = 460, 461
                const float2 t0 = *(const float2*)(x0 + 460);
                const float2 t1 = *(const float2*)(x1 + 460);
                const float2 t2 = *(const float2*)(x2 + 460);
                const float2 t3 = *(const float2*)(x3 + 460);
                const float2 w0 = __ldg((const float2*)(wb + 460 * 120));
                const float2 w1 = __ldg((const float2*)(wb + 461 * 120));
                acc[0][0] += t0.x * w0.x + t0.y * w1.x;
                acc[1][0] += t0.x * w0.y + t0.y * w1.y;
                acc[0][1] += t1.x * w0.x + t1.y * w1.x;
                acc[1][1] += t1.x * w0.y + t1.y * w1.y;
                acc[0][2] += t2.x * w0.x + t2.y * w1.x;
                acc[1][2] += t2.x * w0.y + t2.y * w1.y;
                acc[0][3] += t3.x * w0.x + t3.y * w1.x;
                acc[1][3] += t3.x * w0.y + t3.y * w1.y;
                // write partials to scratch (t3/t1 region of S1 is dead)
                float* scr = S1 + 2048 + (jg * 2 + bq) * 8;
                scr[0] = acc[0][0]; scr[1] = acc[1][0];
                scr[2] = acc[0][1]; scr[3] = acc[1][1];
                scr[4] = acc[0][2]; scr[5] = acc[1][2];
                scr[6] = acc[0][3]; scr[7] = acc[1][3];
            }
        }
        __syncthreads();
        if (active && kh == 0) {
            const int j0 = jg * 2;
            const float* scr = S1 + 2048 + (jg * 2 + bq) * 8;
            const float bfa = s_small[O_BF1 + j0];
            const float bfb = s_small[O_BF1 + j0 + 1];
            float r00 = acc[0][0] + scr[0] + bfa, r10 = acc[1][0] + scr[1] + bfb;
            float r01 = acc[0][1] + scr[2] + bfa, r11 = acc[1][1] + scr[3] + bfb;
            float r02 = acc[0][2] + scr[4] + bfa, r12 = acc[1][2] + scr[5] + bfb;
            float r03 = acc[0][3] + scr[6] + bfa, r13 = acc[1][3] + scr[7] + bfb;
            // careful: h1 region overlaps scratch? h1 idx < 8*124=992 < 2048 OK
            S1[(bq * 4 + 0) * H1S + j0]     = elu1(r00);
            S1[(bq * 4 + 0) * H1S + j0 + 1] = elu1(r10);
            S1[(bq * 4 + 1) * H1S + j0]     = elu1(r01);
            S1[(bq * 4 + 1) * H1S + j0 + 1] = elu1(r11);
            S1[(bq * 4 + 2) * H1S + j0]     = elu1(r02);
            S1[(bq * 4 + 2) * H1S + j0 + 1] = elu1(r12);
            S1[(bq * 4 + 3) * H1S + j0]     = elu1(r03);
            S1[(bq * 4 + 3) * H1S + j0 + 1] = elu1(r13);
        }
    }
    __syncthreads();

    // ========== FC2: h1[8,120] @ Wf2[120,84] + bf2 -> elu -> S2 ======
    if (tid < 336) {
        const int b = tid & 7, jg = tid >> 3;   // jg 0..41
        const int j0 = jg * 2;
        float2 acc = make_float2(s_small[O_BF2 + j0], s_small[O_BF2 + j0 + 1]);
        const float* xin = S1 + b * H1S;
        const float* wb  = Wf2 + j0;
        #pragma unroll 2
        for (int k = 0; k < 120; k += 4) {
            const float4 v  = *(const float4*)(xin + k);
            const float2 w0 = __ldg((const float2*)(wb + (k + 0) * 84));
            const float2 w1 = __ldg((const float2*)(wb + (k + 1) * 84));
            const float2 w2 = __ldg((const float2*)(wb + (k + 2) * 84));
            const float2 w3 = __ldg((const float2*)(wb + (k + 3) * 84));
            acc.x += v.x * w0.x + v.y * w1.x + v.z * w2.x + v.w * w3.x;
            acc.y += v.x * w0.y + v.y * w1.y + v.z * w2.y + v.w * w3.y;
        }
        S2[b * H2S + j0 + 0] = elu1(acc.x);
        S2[b * H2S + j0 + 1] = elu1(acc.y);
    }
    __syncthreads();

    // ========== FC3: h2[8,84] @ Wf3[84,10] + bf3 -> out ==============
    if (tid < 80) {
        const int b = tid & 7, j = tid >> 3;    // j 0..9
        float acc = s_small[O_BF3 + j];
        const float* xin = S2 + b * H2S;
        #pragma unroll 3
        for (int k = 0; k < 84; k += 4) {
            const float4 v = *(const float4*)(xin + k);
            acc += v.x * __ldg(Wf3 + (k + 0) * 10 + j);
            acc += v.y * __ldg(Wf3 + (k + 1) * 10 + j);
            acc += v.z * __ldg(Wf3 + (k + 2) * 10 + j);
            acc += v.w * __ldg(Wf3 + (k + 3) * 10 + j);
        }
        const int g = b0 + b;
        if (g < B) out[(size_t)g * 10 + j] = acc;
    }
}

// =====================================================================
extern "C" void kernel_launch(void* const* d_in, const int* in_sizes, int n_in,
                              void* d_out, int out_size) {
    const float* x   = (const float*)d_in[0];
    const void*  ei  = d_in[1];
    const float* W1  = (const float*)d_in[2];
    const float* b1  = (const float*)d_in[3];
    const float* W2  = (const float*)d_in[4];
    const float* b2  = (const float*)d_in[5];
    const float* W3  = (const float*)d_in[6];
    const float* b3  = (const float*)d_in[7];
    const float* Wf1 = (const float*)d_in[8];
    const float* bf1 = (const float*)d_in[9];
    const float* Wf2 = (const float*)d_in[10];
    const float* bf2 = (const float*)d_in[11];
    const float* Wf3 = (const float*)d_in[12];
    const float* bf3 = (const float*)d_in[13];
    float* out = (float*)d_out;

    const int B = in_sizes[0] / (NN * 12);
    const int E = in_sizes[1] / 2;

    prep_kernel<<<1, 256>>>(ei, E);

    static int smem_set = 0;
    if (!smem_set) {
        cudaFuncSetAttribute(gcn_fused_kernel,
                             cudaFuncAttributeMaxDynamicSharedMemorySize,
                             SM_BYTES);
        smem_set = 1;
    }

    const int blocks = (B + BT - 1) / BT;
    gcn_fused_kernel<<<blocks, THREADS, SM_BYTES>>>(
        x, W1, b1, W2, b2, W3, b3, Wf1, bf1, Wf2, bf2, Wf3, bf3,
        out, B);
}